// round 10
// baseline (speedup 1.0000x reference)
#include <cuda_runtime.h>
#include <cuda_fp16.h>
#include <math.h>
#include <stdint.h>

// ---------------- problem constants ----------------
#define NB    8
#define HI_   56
#define WI_   56
#define HO_   28
#define WO_   28
#define NIN   3136
#define NOUT  784
#define DIN   96
#define DOUT  192
#define HID   384
#define RTOT  (NB*NIN)        // 25088
#define ROUT  (NB*NOUT)       // 6272
#define KCONV 864

#define OFF_X     0
#define OFF_AUPS  ((size_t)ROUT*DOUT)
#define OFF_ADOWN (OFF_AUPS + (size_t)NB*NIN*NOUT)

// ---------------- scratch ----------------
__device__ float g_xn  [RTOT*DIN];
__device__ float g_k   [RTOT*DIN];
__device__ float g_v   [RTOT*DOUT];
__device__ float g_xout[ROUT*DOUT];
__device__ float g_lnq [ROUT*DOUT];
__device__ float g_q   [ROUT*DIN];
__device__ float g_p   [RTOT*9];
__device__ float g_cs  [ROUT];
__device__ float g_h   [ROUT*HID];
__device__ float g_h2  [ROUT*DOUT];
__device__ float g_ai  [ROUT*KCONV];
__device__ float g_wt  [DOUT*KCONV];

// ---------------- helpers ----------------
__device__ __forceinline__ uint32_t pack_h2(float a, float b) {
    __half2 h = __floats2half2_rn(a, b);
    return *reinterpret_cast<uint32_t*>(&h);
}
__device__ __forceinline__ void mma_f16(float* c, const uint32_t* a, const uint32_t* b) {
    asm volatile(
        "mma.sync.aligned.m16n8k16.row.col.f32.f16.f16.f32 "
        "{%0,%1,%2,%3}, {%4,%5,%6,%7}, {%8,%9}, {%0,%1,%2,%3};"
        : "+f"(c[0]), "+f"(c[1]), "+f"(c[2]), "+f"(c[3])
        : "r"(a[0]), "r"(a[1]), "r"(a[2]), "r"(a[3]), "r"(b[0]), "r"(b[1]));
}
__device__ __forceinline__ int drmax(int p, int o) {
    int best = -2;
#pragma unroll
    for (int d = -1; d <= 1; ++d) {
        int c = p + d; c = c < 0 ? 0 : (c > 27 ? 27 : c);
        if (c == o) best = d;
    }
    return best;
}

// block-wide LN stats over 192 threads (6 warps). All threads must call.
__device__ __forceinline__ void blockstats192(float v, float* r1, float* r2,
                                              float& mu, float& var) {
    float s1 = v, s2 = v * v;
#pragma unroll
    for (int o = 16; o; o >>= 1) {
        s1 += __shfl_xor_sync(0xffffffffu, s1, o);
        s2 += __shfl_xor_sync(0xffffffffu, s2, o);
    }
    int t = threadIdx.x;
    int wid = t >> 5, lane = t & 31;
    if (lane == 0) { r1[wid] = s1; r2[wid] = s2; }
    __syncthreads();
    if (t == 0) {
        float a = 0.f, c = 0.f;
        for (int w = 0; w < 6; ++w) { a += r1[w]; c += r2[w]; }
        r1[0] = a; r2[0] = c;
    }
    __syncthreads();
    mu  = r1[0] / (float)DOUT;
    var = r2[0] / (float)DOUT - mu * mu;
    __syncthreads();   // allow r1/r2 reuse
}

// ---------------- tensor-core fp16 GEMM, software-pipelined ----------------
// C[M,N] = A[M,K] @ B[N,K]^T. m16n8k16 f16, fp32 accum. BN=64, BK=32.
// Register-staged double-buffered smem; 1 syncthreads per K-tile.
#define BKP2 20
template<int BM, int EPI>
__global__ void __launch_bounds__(BM*2) gemm_mma(const float* __restrict__ A,
                                                 const float* __restrict__ Bw,
                                                 const float* __restrict__ bias,
                                                 float* __restrict__ C,
                                                 int M, int N, int K) {
    __shared__ uint32_t As[2][BM * BKP2];
    __shared__ uint32_t Bs[2][64 * BKP2];

    const int NT = BM * 2;
    const int A_LD = (BM * 8) / (BM * 2);
    const int B_LD = 512 / (BM * 2);

    const int tid = threadIdx.x;
    const int wid = tid >> 5;
    const int lane = tid & 31;
    const int gid = lane >> 2, tig = lane & 3;
    const int WM = BM / 32;
    const int wm = wid % WM, wn = wid / WM;
    const int m_base = wm * 32, n_base = wn * 32;

    const int bm0 = blockIdx.y * BM;
    const int bn0 = blockIdx.x * 64;

    float4 ra[A_LD], rb[B_LD];

    float acc[2][4][4];
#pragma unroll
    for (int i = 0; i < 2; ++i)
#pragma unroll
        for (int j = 0; j < 4; ++j)
#pragma unroll
            for (int e = 0; e < 4; ++e) acc[i][j][e] = 0.f;

    auto ld_regs = [&](int k0) {
#pragma unroll
        for (int l = 0; l < A_LD; ++l) {
            int f = tid + l * NT;
            int row = f >> 3, ch = f & 7;
            ra[l] = *(const float4*)&A[(size_t)(bm0 + row) * K + k0 + ch * 4];
        }
#pragma unroll
        for (int l = 0; l < B_LD; ++l) {
            int f = tid + l * NT;
            int row = f >> 3, ch = f & 7;
            rb[l] = (bn0 + row < N)
                  ? *(const float4*)&Bw[(size_t)(bn0 + row) * K + k0 + ch * 4]
                  : make_float4(0.f, 0.f, 0.f, 0.f);
        }
    };
    auto st_smem = [&](int s) {
#pragma unroll
        for (int l = 0; l < A_LD; ++l) {
            int f = tid + l * NT;
            int row = f >> 3, ch = f & 7;
            uint32_t* d = &As[s][row * BKP2 + ch * 2];
            d[0] = pack_h2(ra[l].x, ra[l].y);
            d[1] = pack_h2(ra[l].z, ra[l].w);
        }
#pragma unroll
        for (int l = 0; l < B_LD; ++l) {
            int f = tid + l * NT;
            int row = f >> 3, ch = f & 7;
            uint32_t* d = &Bs[s][row * BKP2 + ch * 2];
            d[0] = pack_h2(rb[l].x, rb[l].y);
            d[1] = pack_h2(rb[l].z, rb[l].w);
        }
    };

    const int KT = K >> 5;
    ld_regs(0);
    st_smem(0);
    __syncthreads();

    for (int kt = 0; kt < KT; ++kt) {
        const int s = kt & 1;
        if (kt + 1 < KT) ld_regs((kt + 1) << 5);
#pragma unroll
        for (int ks = 0; ks < 2; ++ks) {
            const int kk = ks * 8;
            uint32_t af[2][4], bf[4][2];
#pragma unroll
            for (int mi = 0; mi < 2; ++mi) {
                const uint32_t* base = &As[s][(m_base + mi * 16 + gid) * BKP2 + kk + tig];
                af[mi][0] = base[0];
                af[mi][1] = base[8 * BKP2];
                af[mi][2] = base[4];
                af[mi][3] = base[8 * BKP2 + 4];
            }
#pragma unroll
            for (int ni = 0; ni < 4; ++ni) {
                const uint32_t* base = &Bs[s][(n_base + ni * 8 + gid) * BKP2 + kk + tig];
                bf[ni][0] = base[0];
                bf[ni][1] = base[4];
            }
#pragma unroll
            for (int mi = 0; mi < 2; ++mi)
#pragma unroll
                for (int ni = 0; ni < 4; ++ni)
                    mma_f16(acc[mi][ni], af[mi], bf[ni]);
        }
        if (kt + 1 < KT) {
            st_smem(s ^ 1);
            __syncthreads();
        }
    }

#pragma unroll
    for (int mi = 0; mi < 2; ++mi) {
#pragma unroll
        for (int ni = 0; ni < 4; ++ni) {
            int col = bn0 + n_base + ni * 8 + tig * 2;
            if (col >= N) continue;
            float b0 = 0.f, b1 = 0.f;
            if (EPI >= 1) { b0 = bias[col]; b1 = bias[col + 1]; }
#pragma unroll
            for (int half = 0; half < 2; ++half) {
                int r = bm0 + m_base + mi * 16 + gid + half * 8;
                float v0 = acc[mi][ni][half * 2 + 0] + b0;
                float v1 = acc[mi][ni][half * 2 + 1] + b1;
                if (EPI == 2) {
                    v0 = 0.5f * v0 * (1.0f + erff(v0 * 0.70710678118654752f));
                    v1 = 0.5f * v1 * (1.0f + erff(v1 * 0.70710678118654752f));
                }
                *(float2*)&C[(size_t)r * N + col] = make_float2(v0, v1);
            }
        }
    }
}

// ---------------- LN over DIN (input norm) ----------------
__global__ void __launch_bounds__(DIN) ln_in_kernel(const float* __restrict__ in,
                                                    const float* __restrict__ gg,
                                                    const float* __restrict__ bb,
                                                    float* __restrict__ out) {
    __shared__ float r1[3], r2[3];
    int row = blockIdx.x;
    int t = threadIdx.x;
    float v = in[(size_t)row * DIN + t];
    float s1 = v, s2 = v * v;
#pragma unroll
    for (int o = 16; o; o >>= 1) {
        s1 += __shfl_xor_sync(0xffffffffu, s1, o);
        s2 += __shfl_xor_sync(0xffffffffu, s2, o);
    }
    int wid = t >> 5, lane = t & 31;
    if (lane == 0) { r1[wid] = s1; r2[wid] = s2; }
    __syncthreads();
    if (t == 0) {
        float a = 0.f, c = 0.f;
        for (int w = 0; w < 3; ++w) { a += r1[w]; c += r2[w]; }
        r1[0] = a; r2[0] = c;
    }
    __syncthreads();
    float mu  = r1[0] / (float)DIN;
    float var = r2[0] / (float)DIN - mu * mu;
    out[(size_t)row * DIN + t] = (v - mu) * rsqrtf(var + 1e-5f) * gg[t] + bb[t];
}

// ---------------- seed LN: xout = LN_out(conv), lnq = LN_out(xout) ----------------
__global__ void __launch_bounds__(DOUT) ln_seed_kernel(const float* __restrict__ in,
                                                       const float* __restrict__ gg,
                                                       const float* __restrict__ bb) {
    __shared__ float r1[6], r2[6];
    int row = blockIdx.x;
    int t = threadIdx.x;
    size_t idx = (size_t)row * DOUT + t;
    float v = in[idx];
    float mu, var;
    blockstats192(v, r1, r2, mu, var);
    float y = (v - mu) * rsqrtf(var + 1e-5f) * gg[t] + bb[t];
    g_xout[idx] = y;
    blockstats192(y, r1, r2, mu, var);
    g_lnq[idx] = (y - mu) * rsqrtf(var + 1e-5f) * gg[t] + bb[t];
}

// ---------------- mlp LN: xout += LN_ml(h2); then lnq=LN_out(xout) or mirror ----------------
template<bool LAST>
__global__ void __launch_bounds__(DOUT) ln_mlp_kernel(const float* __restrict__ gml,
                                                      const float* __restrict__ bml,
                                                      const float* __restrict__ gout,
                                                      const float* __restrict__ bout,
                                                      float* __restrict__ mirror) {
    __shared__ float r1[6], r2[6];
    int row = blockIdx.x;
    int t = threadIdx.x;
    size_t idx = (size_t)row * DOUT + t;
    float v = g_h2[idx];
    float mu, var;
    blockstats192(v, r1, r2, mu, var);
    float y = (v - mu) * rsqrtf(var + 1e-5f) * gml[t] + bml[t];
    float nv = g_xout[idx] + y;
    g_xout[idx] = nv;
    if (LAST) {
        mirror[idx] = nv;
    } else {
        blockstats192(nv, r1, r2, mu, var);
        g_lnq[idx] = (nv - mu) * rsqrtf(var + 1e-5f) * gout[t] + bout[t];
    }
}

// ---------------- conv setup: vectorized im2col + weight reorder (float4/thread) ----------------
#define NI4   (ROUT*KCONV/4)
#define NW4   (DOUT*KCONV/4)
__global__ void prep_kernel(const float* __restrict__ x, const float* __restrict__ conv_w) {
    int idx = blockIdx.x * blockDim.x + threadIdx.x;
    if (idx < NI4) {
        int r  = idx / 216;
        int c4 = idx % 216;
        int tap = c4 / 24;
        int i   = (c4 % 24) * 4;
        int b = r / NOUT, m = r % NOUT;
        int orr = m / WO_, occ = m % WO_;
        int ir = 2 * orr + tap / 3 - 1;
        int ic = 2 * occ + tap % 3 - 1;
        float4 v = make_float4(0.f, 0.f, 0.f, 0.f);
        if (ir >= 0 && ir < HI_ && ic >= 0 && ic < WI_)
            v = *(const float4*)&x[((size_t)b * NIN + ir * WI_ + ic) * DIN + i];
        ((float4*)g_ai)[idx] = v;
    } else if (idx < NI4 + NW4) {
        int j  = idx - NI4;
        int o  = j / 216;
        int c4 = j % 216;
        int tap = c4 / 24;
        int i   = (c4 % 24) * 4;
        const float* wsrc = conv_w + ((size_t)o * DIN + i) * 9 + tap;
        float4 w;
        w.x = wsrc[0]; w.y = wsrc[9]; w.z = wsrc[18]; w.w = wsrc[27];
        ((float4*)g_wt)[j] = w;
    }
}

// ---------------- sparse attention softmax (warp-per-token) ----------------
__global__ void __launch_bounds__(256) attn_kernel(const float* __restrict__ rpb,
                                                   const float* __restrict__ taup) {
    int gw = blockIdx.x * 8 + (threadIdx.x >> 5);
    int lane = threadIdx.x & 31;
    int b = gw / NIN, n = gw % NIN;
    int ir = n / WI_, ic = n % WI_;
    int pr = ir >> 1, pc = ic >> 1;
    const float* kr = &g_k[((size_t)b * NIN + n) * DIN];
    float kv0 = kr[lane], kv1 = kr[lane + 32], kv2 = kr[lane + 64];
    float scale = expf(*taup);
    float l[9];
#pragma unroll
    for (int k = 0; k < 9; ++k) {
        int dr = k / 3 - 1, dc = k % 3 - 1;
        int o_r = min(max(pr + dr, 0), HO_ - 1);
        int o_c = min(max(pc + dc, 0), WO_ - 1);
        bool rep = (dr == drmax(pr, o_r)) && (dc == drmax(pc, o_c));
        float s = -1e30f;
        if (rep) {
            int m = o_r * WO_ + o_c;
            const float* qr = &g_q[((size_t)b * NOUT + m) * DIN];
            float d0 = kv0 * qr[lane] + kv1 * qr[lane + 32] + kv2 * qr[lane + 64];
#pragma unroll
            for (int o = 16; o; o >>= 1) d0 += __shfl_xor_sync(0xffffffffu, d0, o);
            s = d0 * scale + rpb[k];
        }
        l[k] = s;
    }
    float mx = l[0];
#pragma unroll
    for (int k = 1; k < 9; ++k) mx = fmaxf(mx, l[k]);
    float e[9], sum = 0.f;
#pragma unroll
    for (int k = 0; k < 9; ++k) {
        e[k] = (l[k] > -1e29f) ? expf(l[k] - mx) : 0.f;
        sum += e[k];
    }
    float inv = 1.f / sum;
    if (lane == 0) {
        float* pp = &g_p[((size_t)b * NIN + n) * 9];
#pragma unroll
        for (int k = 0; k < 9; ++k) pp[k] = e[k] * inv;
    }
}

// ---------------- gather updates + col sums + LN + residual ----------------
__global__ void __launch_bounds__(DOUT) updates_kernel(const float* __restrict__ g_attn,
                                                       const float* __restrict__ b_attn) {
    __shared__ float sp[36];
    __shared__ int   sn[36];
    __shared__ float r1[6], r2[6], s_inv;
    int bm = blockIdx.x;
    int b = bm / NOUT, m = bm % NOUT;
    int orr = m / WO_, occ = m % WO_;
    int ir0 = max(2 * orr - 2, 0), ir1 = min(2 * orr + 3, HI_ - 1);
    int ic0 = max(2 * occ - 2, 0), ic1 = min(2 * occ + 3, WI_ - 1);
    int nr = ir1 - ir0 + 1, nc = ic1 - ic0 + 1;
    int cnt = nr * nc;
    int t = threadIdx.x;
    if (t < 36) {
        if (t < cnt) {
            int irr = ir0 + t / nc, icc = ic0 + t % nc;
            int n = irr * WI_ + icc;
            int kmax = (drmax(irr >> 1, orr) + 1) * 3 + (drmax(icc >> 1, occ) + 1);
            sp[t] = g_p[((size_t)b * NIN + n) * 9 + kmax];
            sn[t] = n;
        } else {
            sp[t] = 0.f;
            sn[t] = 0;
        }
    }
    __syncthreads();
    if (t == 0) {
        float cs = 0.f;
        for (int j = 0; j < cnt; ++j) cs += sp[j];
        g_cs[bm] = cs;
        s_inv = 1.f / (cs + 1e-8f);
    }
    __syncthreads();
    const float* vb = g_v + (size_t)b * NIN * DOUT;
    float a0 = 0.f, a1 = 0.f, a2 = 0.f, a3 = 0.f;
#pragma unroll
    for (int j = 0; j < 36; j += 4) {
        a0 += sp[j + 0] * vb[(size_t)sn[j + 0] * DOUT + t];
        a1 += sp[j + 1] * vb[(size_t)sn[j + 1] * DOUT + t];
        a2 += sp[j + 2] * vb[(size_t)sn[j + 2] * DOUT + t];
        a3 += sp[j + 3] * vb[(size_t)sn[j + 3] * DOUT + t];
    }
    float u = ((a0 + a1) + (a2 + a3)) * s_inv;
    float mu, var;
    blockstats192(u, r1, r2, mu, var);
    float y = (u - mu) * rsqrtf(var + 1e-5f) * g_attn[t] + b_attn[t];
    g_xout[(size_t)bm * DOUT + t] += y;
}

// ---------------- dense row writer: a_ups & a_down, table-driven ----------------
// Thread t<196 handles one o_r (t/7) and 4 consecutive o_c ((t%7)*4 + j);
// store address is exactly 4t -> fully coalesced float4 stores.
__global__ void __launch_bounds__(256) writeA_kernel(float* __restrict__ aups,
                                                     float* __restrict__ adown) {
    __shared__ float sp[9], sdn[9];
    __shared__ int8_t dm[28 * 28];
    int bn = blockIdx.x;
    int b = bn / NIN, n = bn % NIN;
    int pr = (n / WI_) >> 1, pc = (n % WI_) >> 1;
    int t = threadIdx.x;
    // drmax LUT (identical for all blocks; cheap to rebuild per block)
    for (int i = t; i < 784; i += 256) {
        int p = i / 28, o = i % 28;
        dm[i] = (int8_t)drmax(p, o);
    }
    if (t < 9) {
        float u = g_p[(size_t)bn * 9 + t];
        sp[t] = u;
        int dr = t / 3 - 1, dc = t % 3 - 1;
        int o_r = min(max(pr + dr, 0), HO_ - 1);
        int o_c = min(max(pc + dc, 0), WO_ - 1);
        sdn[t] = u / (g_cs[b * NOUT + o_r * WO_ + o_c] + 1e-8f);
    }
    __syncthreads();
    if (t >= 196) return;
    int o_r = t / 7, g = (t % 7) * 4;
    int dr = dm[pr * 28 + o_r];
    float up[4], dn[4];
#pragma unroll
    for (int j = 0; j < 4; ++j) {
        int dc = dm[pc * 28 + g + j];
        bool valid = (dr >= -1) && (dc >= -1);
        int k = valid ? (dr + 1) * 3 + (dc + 1) : 0;
        up[j] = valid ? sp[k]  : 0.f;
        dn[j] = valid ? sdn[k] : 0.f;
    }
    size_t rb = (size_t)bn * NOUT + (size_t)t * 4;
    *(float4*)&aups[rb]  = *(float4*)up;
    *(float4*)&adown[rb] = *(float4*)dn;
}

// ---------------- host launch ----------------
extern "C" void kernel_launch(void* const* d_in, const int* in_sizes, int n_in,
                              void* d_out, int out_size) {
    const float* x      = (const float*)d_in[0];
    const float* conv_w = (const float*)d_in[1];
    const float* q_w    = (const float*)d_in[2];
    const float* k_w    = (const float*)d_in[3];
    const float* v_w    = (const float*)d_in[4];
    const float* w1     = (const float*)d_in[5];
    const float* b1     = (const float*)d_in[6];
    const float* w2     = (const float*)d_in[7];
    const float* b2     = (const float*)d_in[8];
    const float* ln_in_g  = (const float*)d_in[9];
    const float* ln_in_b  = (const float*)d_in[10];
    const float* ln_out_g = (const float*)d_in[11];
    const float* ln_out_b = (const float*)d_in[12];
    const float* ln_at_g  = (const float*)d_in[13];
    const float* ln_at_b  = (const float*)d_in[14];
    const float* ln_ml_g  = (const float*)d_in[15];
    const float* ln_ml_b  = (const float*)d_in[16];
    const float* tau    = (const float*)d_in[17];
    const float* rpb    = (const float*)d_in[18];
    float* out = (float*)d_out;

    float *pxn, *pk, *pv, *pxout, *plnq, *pq, *ph, *ph2, *pai, *pwt;
    cudaGetSymbolAddress((void**)&pxn,  g_xn);
    cudaGetSymbolAddress((void**)&pk,   g_k);
    cudaGetSymbolAddress((void**)&pv,   g_v);
    cudaGetSymbolAddress((void**)&pxout,g_xout);
    cudaGetSymbolAddress((void**)&plnq, g_lnq);
    cudaGetSymbolAddress((void**)&pq,   g_q);
    cudaGetSymbolAddress((void**)&ph,   g_h);
    cudaGetSymbolAddress((void**)&ph2,  g_h2);
    cudaGetSymbolAddress((void**)&pai,  g_ai);
    cudaGetSymbolAddress((void**)&pwt,  g_wt);

    // ---- head: xn = LN(x); k/v projections; conv seed ----
    ln_in_kernel<<<RTOT, DIN>>>(x, ln_in_g, ln_in_b, pxn);
    gemm_mma<128, 0><<<dim3(2, RTOT / 128), 256>>>(pxn, k_w, nullptr, pk, RTOT, DIN, DIN);
    gemm_mma<128, 0><<<dim3(3, RTOT / 128), 256>>>(pxn, v_w, nullptr, pv, RTOT, DOUT, DIN);

    prep_kernel<<<(NI4 + NW4 + 255) / 256, 256>>>(x, conv_w);
    gemm_mma<128, 0><<<dim3(3, ROUT / 128), 256>>>(pai, pwt, nullptr, ph2, ROUT, DOUT, KCONV);
    ln_seed_kernel<<<ROUT, DOUT>>>(ph2, ln_out_g, ln_out_b);

    for (int it = 0; it < 3; ++it) {
        gemm_mma<64, 0><<<dim3(2, ROUT / 64), 128>>>(plnq, q_w, nullptr, pq, ROUT, DIN, DOUT);
        attn_kernel<<<RTOT / 8, 256>>>(rpb, tau);
        updates_kernel<<<ROUT, DOUT>>>(ln_at_g, ln_at_b);
        gemm_mma<128, 2><<<dim3(6, ROUT / 128), 256>>>(pxout, w1, b1, ph, ROUT, HID, DOUT);
        gemm_mma<128, 1><<<dim3(3, ROUT / 128), 256>>>(ph, w2, b2, ph2, ROUT, DOUT, HID);
        if (it == 2)
            ln_mlp_kernel<true><<<ROUT, DOUT>>>(ln_ml_g, ln_ml_b, ln_out_g, ln_out_b, out + OFF_X);
        else
            ln_mlp_kernel<false><<<ROUT, DOUT>>>(ln_ml_g, ln_ml_b, ln_out_g, ln_out_b, nullptr);
    }

    // ---- dense a_ups / a_down ----
    writeA_kernel<<<RTOT, 256>>>(out + OFF_AUPS, out + OFF_ADOWN);
}

// round 11
// speedup vs baseline: 1.1001x; 1.1001x over previous
#include <cuda_runtime.h>
#include <cuda_fp16.h>
#include <math.h>
#include <stdint.h>

// ---------------- problem constants ----------------
#define NB    8
#define HI_   56
#define WI_   56
#define HO_   28
#define WO_   28
#define NIN   3136
#define NOUT  784
#define DIN   96
#define DOUT  192
#define HID   384
#define RTOT  (NB*NIN)        // 25088
#define ROUT  (NB*NOUT)       // 6272
#define KCONV 864

#define OFF_X     0
#define OFF_AUPS  ((size_t)ROUT*DOUT)
#define OFF_ADOWN (OFF_AUPS + (size_t)NB*NIN*NOUT)

// ---------------- scratch ----------------
__device__ float g_xn  [RTOT*DIN];
__device__ float g_k   [RTOT*DIN];
__device__ float g_v   [RTOT*DOUT];
__device__ float g_xout[ROUT*DOUT];
__device__ float g_lnq [ROUT*DOUT];
__device__ float g_q   [ROUT*DIN];
__device__ float g_p   [RTOT*9];
__device__ float g_cs  [ROUT];
__device__ float g_h   [ROUT*HID];
__device__ float g_h2  [ROUT*DOUT];
__device__ float g_ai  [ROUT*KCONV];
__device__ float g_wt  [DOUT*KCONV];

// ---------------- helpers ----------------
__device__ __forceinline__ uint32_t pack_h2(float a, float b) {
    __half2 h = __floats2half2_rn(a, b);
    return *reinterpret_cast<uint32_t*>(&h);
}
__device__ __forceinline__ void mma_f16(float* c, const uint32_t* a, const uint32_t* b) {
    asm volatile(
        "mma.sync.aligned.m16n8k16.row.col.f32.f16.f16.f32 "
        "{%0,%1,%2,%3}, {%4,%5,%6,%7}, {%8,%9}, {%0,%1,%2,%3};"
        : "+f"(c[0]), "+f"(c[1]), "+f"(c[2]), "+f"(c[3])
        : "r"(a[0]), "r"(a[1]), "r"(a[2]), "r"(a[3]), "r"(b[0]), "r"(b[1]));
}
__device__ __forceinline__ int drmax(int p, int o) {
    int best = -2;
#pragma unroll
    for (int d = -1; d <= 1; ++d) {
        int c = p + d; c = c < 0 ? 0 : (c > 27 ? 27 : c);
        if (c == o) best = d;
    }
    return best;
}

// block-wide LN stats over 192 threads (6 warps). All threads must call.
__device__ __forceinline__ void blockstats192(float v, float* r1, float* r2,
                                              float& mu, float& var) {
    float s1 = v, s2 = v * v;
#pragma unroll
    for (int o = 16; o; o >>= 1) {
        s1 += __shfl_xor_sync(0xffffffffu, s1, o);
        s2 += __shfl_xor_sync(0xffffffffu, s2, o);
    }
    int t = threadIdx.x;
    int wid = t >> 5, lane = t & 31;
    if (lane == 0) { r1[wid] = s1; r2[wid] = s2; }
    __syncthreads();
    if (t == 0) {
        float a = 0.f, c = 0.f;
        for (int w = 0; w < 6; ++w) { a += r1[w]; c += r2[w]; }
        r1[0] = a; r2[0] = c;
    }
    __syncthreads();
    mu  = r1[0] / (float)DOUT;
    var = r2[0] / (float)DOUT - mu * mu;
    __syncthreads();   // allow r1/r2 reuse
}

// ---------------- tensor-core fp16 GEMM, software-pipelined ----------------
// C[M,N] = A[M,K] @ B[N,K]^T. m16n8k16 f16, fp32 accum. BN=64, BK=32.
// Register-staged double-buffered smem; 1 syncthreads per K-tile.
#define BKP2 20
template<int BM, int EPI>
__global__ void __launch_bounds__(BM*2) gemm_mma(const float* __restrict__ A,
                                                 const float* __restrict__ Bw,
                                                 const float* __restrict__ bias,
                                                 float* __restrict__ C,
                                                 int M, int N, int K) {
    __shared__ uint32_t As[2][BM * BKP2];
    __shared__ uint32_t Bs[2][64 * BKP2];

    const int NT = BM * 2;
    const int A_LD = (BM * 8) / (BM * 2);
    const int B_LD = 512 / (BM * 2);

    const int tid = threadIdx.x;
    const int wid = tid >> 5;
    const int lane = tid & 31;
    const int gid = lane >> 2, tig = lane & 3;
    const int WM = BM / 32;
    const int wm = wid % WM, wn = wid / WM;
    const int m_base = wm * 32, n_base = wn * 32;

    const int bm0 = blockIdx.y * BM;
    const int bn0 = blockIdx.x * 64;

    float4 ra[A_LD], rb[B_LD];

    float acc[2][4][4];
#pragma unroll
    for (int i = 0; i < 2; ++i)
#pragma unroll
        for (int j = 0; j < 4; ++j)
#pragma unroll
            for (int e = 0; e < 4; ++e) acc[i][j][e] = 0.f;

    auto ld_regs = [&](int k0) {
#pragma unroll
        for (int l = 0; l < A_LD; ++l) {
            int f = tid + l * NT;
            int row = f >> 3, ch = f & 7;
            ra[l] = *(const float4*)&A[(size_t)(bm0 + row) * K + k0 + ch * 4];
        }
#pragma unroll
        for (int l = 0; l < B_LD; ++l) {
            int f = tid + l * NT;
            int row = f >> 3, ch = f & 7;
            rb[l] = (bn0 + row < N)
                  ? *(const float4*)&Bw[(size_t)(bn0 + row) * K + k0 + ch * 4]
                  : make_float4(0.f, 0.f, 0.f, 0.f);
        }
    };
    auto st_smem = [&](int s) {
#pragma unroll
        for (int l = 0; l < A_LD; ++l) {
            int f = tid + l * NT;
            int row = f >> 3, ch = f & 7;
            uint32_t* d = &As[s][row * BKP2 + ch * 2];
            d[0] = pack_h2(ra[l].x, ra[l].y);
            d[1] = pack_h2(ra[l].z, ra[l].w);
        }
#pragma unroll
        for (int l = 0; l < B_LD; ++l) {
            int f = tid + l * NT;
            int row = f >> 3, ch = f & 7;
            uint32_t* d = &Bs[s][row * BKP2 + ch * 2];
            d[0] = pack_h2(rb[l].x, rb[l].y);
            d[1] = pack_h2(rb[l].z, rb[l].w);
        }
    };

    const int KT = K >> 5;
    ld_regs(0);
    st_smem(0);
    __syncthreads();

    for (int kt = 0; kt < KT; ++kt) {
        const int s = kt & 1;
        if (kt + 1 < KT) ld_regs((kt + 1) << 5);
#pragma unroll
        for (int ks = 0; ks < 2; ++ks) {
            const int kk = ks * 8;
            uint32_t af[2][4], bf[4][2];
#pragma unroll
            for (int mi = 0; mi < 2; ++mi) {
                const uint32_t* base = &As[s][(m_base + mi * 16 + gid) * BKP2 + kk + tig];
                af[mi][0] = base[0];
                af[mi][1] = base[8 * BKP2];
                af[mi][2] = base[4];
                af[mi][3] = base[8 * BKP2 + 4];
            }
#pragma unroll
            for (int ni = 0; ni < 4; ++ni) {
                const uint32_t* base = &Bs[s][(n_base + ni * 8 + gid) * BKP2 + kk + tig];
                bf[ni][0] = base[0];
                bf[ni][1] = base[4];
            }
#pragma unroll
            for (int mi = 0; mi < 2; ++mi)
#pragma unroll
                for (int ni = 0; ni < 4; ++ni)
                    mma_f16(acc[mi][ni], af[mi], bf[ni]);
        }
        if (kt + 1 < KT) {
            st_smem(s ^ 1);
            __syncthreads();
        }
    }

#pragma unroll
    for (int mi = 0; mi < 2; ++mi) {
#pragma unroll
        for (int ni = 0; ni < 4; ++ni) {
            int col = bn0 + n_base + ni * 8 + tig * 2;
            if (col >= N) continue;
            float b0 = 0.f, b1 = 0.f;
            if (EPI >= 1) { b0 = bias[col]; b1 = bias[col + 1]; }
#pragma unroll
            for (int half = 0; half < 2; ++half) {
                int r = bm0 + m_base + mi * 16 + gid + half * 8;
                float v0 = acc[mi][ni][half * 2 + 0] + b0;
                float v1 = acc[mi][ni][half * 2 + 1] + b1;
                if (EPI == 2) {
                    v0 = 0.5f * v0 * (1.0f + erff(v0 * 0.70710678118654752f));
                    v1 = 0.5f * v1 * (1.0f + erff(v1 * 0.70710678118654752f));
                }
                *(float2*)&C[(size_t)r * N + col] = make_float2(v0, v1);
            }
        }
    }
}

// ---------------- LN over DIN (input norm) ----------------
__global__ void __launch_bounds__(DIN) ln_in_kernel(const float* __restrict__ in,
                                                    const float* __restrict__ gg,
                                                    const float* __restrict__ bb,
                                                    float* __restrict__ out) {
    __shared__ float r1[3], r2[3];
    int row = blockIdx.x;
    int t = threadIdx.x;
    float v = in[(size_t)row * DIN + t];
    float s1 = v, s2 = v * v;
#pragma unroll
    for (int o = 16; o; o >>= 1) {
        s1 += __shfl_xor_sync(0xffffffffu, s1, o);
        s2 += __shfl_xor_sync(0xffffffffu, s2, o);
    }
    int wid = t >> 5, lane = t & 31;
    if (lane == 0) { r1[wid] = s1; r2[wid] = s2; }
    __syncthreads();
    if (t == 0) {
        float a = 0.f, c = 0.f;
        for (int w = 0; w < 3; ++w) { a += r1[w]; c += r2[w]; }
        r1[0] = a; r2[0] = c;
    }
    __syncthreads();
    float mu  = r1[0] / (float)DIN;
    float var = r2[0] / (float)DIN - mu * mu;
    out[(size_t)row * DIN + t] = (v - mu) * rsqrtf(var + 1e-5f) * gg[t] + bb[t];
}

// ---------------- seed LN: xout = LN_out(conv), lnq = LN_out(xout) ----------------
__global__ void __launch_bounds__(DOUT) ln_seed_kernel(const float* __restrict__ in,
                                                       const float* __restrict__ gg,
                                                       const float* __restrict__ bb) {
    __shared__ float r1[6], r2[6];
    int row = blockIdx.x;
    int t = threadIdx.x;
    size_t idx = (size_t)row * DOUT + t;
    float v = in[idx];
    float mu, var;
    blockstats192(v, r1, r2, mu, var);
    float y = (v - mu) * rsqrtf(var + 1e-5f) * gg[t] + bb[t];
    g_xout[idx] = y;
    blockstats192(y, r1, r2, mu, var);
    g_lnq[idx] = (y - mu) * rsqrtf(var + 1e-5f) * gg[t] + bb[t];
}

// ---------------- mlp LN: xout += LN_ml(h2); then lnq=LN_out(xout) or mirror ----------------
template<bool LAST>
__global__ void __launch_bounds__(DOUT) ln_mlp_kernel(const float* __restrict__ gml,
                                                      const float* __restrict__ bml,
                                                      const float* __restrict__ gout,
                                                      const float* __restrict__ bout,
                                                      float* __restrict__ mirror) {
    __shared__ float r1[6], r2[6];
    int row = blockIdx.x;
    int t = threadIdx.x;
    size_t idx = (size_t)row * DOUT + t;
    float v = g_h2[idx];
    float mu, var;
    blockstats192(v, r1, r2, mu, var);
    float y = (v - mu) * rsqrtf(var + 1e-5f) * gml[t] + bml[t];
    float nv = g_xout[idx] + y;
    g_xout[idx] = nv;
    if (LAST) {
        mirror[idx] = nv;
    } else {
        blockstats192(nv, r1, r2, mu, var);
        g_lnq[idx] = (nv - mu) * rsqrtf(var + 1e-5f) * gout[t] + bout[t];
    }
}

// ---------------- conv setup: vectorized im2col + weight reorder (float4/thread) ----------------
#define NI4   (ROUT*KCONV/4)
#define NW4   (DOUT*KCONV/4)
__global__ void prep_kernel(const float* __restrict__ x, const float* __restrict__ conv_w) {
    int idx = blockIdx.x * blockDim.x + threadIdx.x;
    if (idx < NI4) {
        int r  = idx / 216;
        int c4 = idx % 216;
        int tap = c4 / 24;
        int i   = (c4 % 24) * 4;
        int b = r / NOUT, m = r % NOUT;
        int orr = m / WO_, occ = m % WO_;
        int ir = 2 * orr + tap / 3 - 1;
        int ic = 2 * occ + tap % 3 - 1;
        float4 v = make_float4(0.f, 0.f, 0.f, 0.f);
        if (ir >= 0 && ir < HI_ && ic >= 0 && ic < WI_)
            v = *(const float4*)&x[((size_t)b * NIN + ir * WI_ + ic) * DIN + i];
        ((float4*)g_ai)[idx] = v;
    } else if (idx < NI4 + NW4) {
        int j  = idx - NI4;
        int o  = j / 216;
        int c4 = j % 216;
        int tap = c4 / 24;
        int i   = (c4 % 24) * 4;
        const float* wsrc = conv_w + ((size_t)o * DIN + i) * 9 + tap;
        float4 w;
        w.x = wsrc[0]; w.y = wsrc[9]; w.z = wsrc[18]; w.w = wsrc[27];
        ((float4*)g_wt)[j] = w;
    }
}

// ---------------- sparse attention softmax (warp-per-token) ----------------
__global__ void __launch_bounds__(256) attn_kernel(const float* __restrict__ rpb,
                                                   const float* __restrict__ taup) {
    int gw = blockIdx.x * 8 + (threadIdx.x >> 5);
    int lane = threadIdx.x & 31;
    int b = gw / NIN, n = gw % NIN;
    int ir = n / WI_, ic = n % WI_;
    int pr = ir >> 1, pc = ic >> 1;
    const float* kr = &g_k[((size_t)b * NIN + n) * DIN];
    float kv0 = kr[lane], kv1 = kr[lane + 32], kv2 = kr[lane + 64];
    float scale = expf(*taup);
    float l[9];
#pragma unroll
    for (int k = 0; k < 9; ++k) {
        int dr = k / 3 - 1, dc = k % 3 - 1;
        int o_r = min(max(pr + dr, 0), HO_ - 1);
        int o_c = min(max(pc + dc, 0), WO_ - 1);
        bool rep = (dr == drmax(pr, o_r)) && (dc == drmax(pc, o_c));
        float s = -1e30f;
        if (rep) {
            int m = o_r * WO_ + o_c;
            const float* qr = &g_q[((size_t)b * NOUT + m) * DIN];
            float d0 = kv0 * qr[lane] + kv1 * qr[lane + 32] + kv2 * qr[lane + 64];
#pragma unroll
            for (int o = 16; o; o >>= 1) d0 += __shfl_xor_sync(0xffffffffu, d0, o);
            s = d0 * scale + rpb[k];
        }
        l[k] = s;
    }
    float mx = l[0];
#pragma unroll
    for (int k = 1; k < 9; ++k) mx = fmaxf(mx, l[k]);
    float e[9], sum = 0.f;
#pragma unroll
    for (int k = 0; k < 9; ++k) {
        e[k] = (l[k] > -1e29f) ? expf(l[k] - mx) : 0.f;
        sum += e[k];
    }
    float inv = 1.f / sum;
    if (lane == 0) {
        float* pp = &g_p[((size_t)b * NIN + n) * 9];
#pragma unroll
        for (int k = 0; k < 9; ++k) pp[k] = e[k] * inv;
    }
}

// ---------------- updates: 2x2 slot quad per block ----------------
// Union window 8x8 = 64 tokens streamed once, 4 per-slot weight tables.
// Grid = NB * 14 * 14. Zero-padded weights keep per-slot serial sums
// bit-equal to per-slot window traversal (x + 0.0f == x for x != -0).
__global__ void __launch_bounds__(DOUT) updates_kernel(const float* __restrict__ g_attn,
                                                       const float* __restrict__ b_attn) {
    __shared__ float sw[4][64];
    __shared__ int   snn[64];
    __shared__ float sinv[4];
    __shared__ float r1[6], r2[6];
    int bm = blockIdx.x;
    int b = bm / 196;
    int rem = bm % 196;
    int orr = (rem / 14) * 2, occ = (rem % 14) * 2;
    int ir0 = max(2 * orr - 2, 0), ir1 = min(2 * orr + 5, HI_ - 1);
    int ic0 = max(2 * occ - 2, 0), ic1 = min(2 * occ + 5, WI_ - 1);
    int nr = ir1 - ir0 + 1, nc = ic1 - ic0 + 1;
    int cnt = nr * nc;
    int t = threadIdx.x;
    if (t < 64) {
        if (t < cnt) {
            int irr = ir0 + t / nc, icc = ic0 + t % nc;
            int n = irr * WI_ + icc;
            snn[t] = n;
            const float* pp = &g_p[((size_t)b * NIN + n) * 9];
            int pr = irr >> 1, pc = icc >> 1;
#pragma unroll
            for (int s = 0; s < 4; ++s) {
                int dr = drmax(pr, orr + (s >> 1));
                int dc = drmax(pc, occ + (s & 1));
                float w = 0.f;
                if (dr >= -1 && dc >= -1) w = pp[(dr + 1) * 3 + (dc + 1)];
                sw[s][t] = w;
            }
        } else {
            snn[t] = 0;
#pragma unroll
            for (int s = 0; s < 4; ++s) sw[s][t] = 0.f;
        }
    }
    __syncthreads();
    if (t < 4) {
        float cs = 0.f;
        for (int j = 0; j < cnt; ++j) cs += sw[t][j];
        sinv[t] = 1.f / (cs + 1e-8f);
        g_cs[b * NOUT + (orr + (t >> 1)) * WO_ + occ + (t & 1)] = cs;
    }
    __syncthreads();
    const float* vb = g_v + (size_t)b * NIN * DOUT;
    float a0 = 0.f, a1 = 0.f, a2 = 0.f, a3 = 0.f;
#pragma unroll 4
    for (int j = 0; j < 64; ++j) {
        float v = vb[(size_t)snn[j] * DOUT + t];
        a0 += sw[0][j] * v;
        a1 += sw[1][j] * v;
        a2 += sw[2][j] * v;
        a3 += sw[3][j] * v;
    }
    float u[4] = { a0 * sinv[0], a1 * sinv[1], a2 * sinv[2], a3 * sinv[3] };
    float ga = g_attn[t], ba = b_attn[t];
#pragma unroll
    for (int s = 0; s < 4; ++s) {
        float mu, var;
        blockstats192(u[s], r1, r2, mu, var);
        float y = (u[s] - mu) * rsqrtf(var + 1e-5f) * ga + ba;
        int row = b * NOUT + (orr + (s >> 1)) * WO_ + occ + (s & 1);
        g_xout[(size_t)row * DOUT + t] += y;
    }
}

// ---------------- dense row writer: a_ups & a_down in one pass (round-9) ----------------
__global__ void __launch_bounds__(256) writeA_kernel(float* __restrict__ aups,
                                                     float* __restrict__ adown) {
    __shared__ float sp[9];
    int bn = blockIdx.x;
    int b = bn / NIN, n = bn % NIN;
    int pr = (n / WI_) >> 1, pc = (n % WI_) >> 1;
    int t = threadIdx.x;
    if (t < 9) sp[t] = g_p[(size_t)bn * 9 + t];
    __syncthreads();
    if (t >= 196) return;
    size_t rb = (size_t)bn * NOUT;
    float up[4], dn[4];
#pragma unroll
    for (int j = 0; j < 4; ++j) {
        int m = t * 4 + j;
        int o_r = m / WO_, o_c = m % WO_;
        int dr = drmax(pr, o_r), dc = drmax(pc, o_c);
        float u = 0.f, d = 0.f;
        if (dr >= -1 && dc >= -1) {
            u = sp[(dr + 1) * 3 + (dc + 1)];
            d = u / (g_cs[b * NOUT + m] + 1e-8f);
        }
        up[j] = u; dn[j] = d;
    }
    *(float4*)&aups[rb + t * 4]  = *(float4*)up;
    *(float4*)&adown[rb + t * 4] = *(float4*)dn;
}

// ---------------- host launch ----------------
extern "C" void kernel_launch(void* const* d_in, const int* in_sizes, int n_in,
                              void* d_out, int out_size) {
    const float* x      = (const float*)d_in[0];
    const float* conv_w = (const float*)d_in[1];
    const float* q_w    = (const float*)d_in[2];
    const float* k_w    = (const float*)d_in[3];
    const float* v_w    = (const float*)d_in[4];
    const float* w1     = (const float*)d_in[5];
    const float* b1     = (const float*)d_in[6];
    const float* w2     = (const float*)d_in[7];
    const float* b2     = (const float*)d_in[8];
    const float* ln_in_g  = (const float*)d_in[9];
    const float* ln_in_b  = (const float*)d_in[10];
    const float* ln_out_g = (const float*)d_in[11];
    const float* ln_out_b = (const float*)d_in[12];
    const float* ln_at_g  = (const float*)d_in[13];
    const float* ln_at_b  = (const float*)d_in[14];
    const float* ln_ml_g  = (const float*)d_in[15];
    const float* ln_ml_b  = (const float*)d_in[16];
    const float* tau    = (const float*)d_in[17];
    const float* rpb    = (const float*)d_in[18];
    float* out = (float*)d_out;

    float *pxn, *pk, *pv, *pxout, *plnq, *pq, *ph, *ph2, *pai, *pwt;
    cudaGetSymbolAddress((void**)&pxn,  g_xn);
    cudaGetSymbolAddress((void**)&pk,   g_k);
    cudaGetSymbolAddress((void**)&pv,   g_v);
    cudaGetSymbolAddress((void**)&pxout,g_xout);
    cudaGetSymbolAddress((void**)&plnq, g_lnq);
    cudaGetSymbolAddress((void**)&pq,   g_q);
    cudaGetSymbolAddress((void**)&ph,   g_h);
    cudaGetSymbolAddress((void**)&ph2,  g_h2);
    cudaGetSymbolAddress((void**)&pai,  g_ai);
    cudaGetSymbolAddress((void**)&pwt,  g_wt);

    // ---- head: xn = LN(x); k/v projections; conv seed ----
    ln_in_kernel<<<RTOT, DIN>>>(x, ln_in_g, ln_in_b, pxn);
    gemm_mma<128, 0><<<dim3(2, RTOT / 128), 256>>>(pxn, k_w, nullptr, pk, RTOT, DIN, DIN);
    gemm_mma<128, 0><<<dim3(3, RTOT / 128), 256>>>(pxn, v_w, nullptr, pv, RTOT, DOUT, DIN);

    prep_kernel<<<(NI4 + NW4 + 255) / 256, 256>>>(x, conv_w);
    gemm_mma<128, 0><<<dim3(3, ROUT / 128), 256>>>(pai, pwt, nullptr, ph2, ROUT, DOUT, KCONV);
    ln_seed_kernel<<<ROUT, DOUT>>>(ph2, ln_out_g, ln_out_b);

    for (int it = 0; it < 3; ++it) {
        gemm_mma<64, 0><<<dim3(2, ROUT / 64), 128>>>(plnq, q_w, nullptr, pq, ROUT, DIN, DOUT);
        attn_kernel<<<RTOT / 8, 256>>>(rpb, tau);
        updates_kernel<<<NB * 196, DOUT>>>(ln_at_g, ln_at_b);
        gemm_mma<128, 2><<<dim3(6, ROUT / 128), 256>>>(pxout, w1, b1, ph, ROUT, HID, DOUT);
        gemm_mma<128, 1><<<dim3(3, ROUT / 128), 256>>>(ph, w2, b2, ph2, ROUT, DOUT, HID);
        if (it == 2)
            ln_mlp_kernel<true><<<ROUT, DOUT>>>(ln_ml_g, ln_ml_b, ln_out_g, ln_out_b, out + OFF_X);
        else
            ln_mlp_kernel<false><<<ROUT, DOUT>>>(ln_ml_g, ln_ml_b, ln_out_g, ln_out_b, nullptr);
    }

    // ---- dense a_ups / a_down ----
    writeA_kernel<<<RTOT, 256>>>(out + OFF_AUPS, out + OFF_ADOWN);
}